// round 1
// baseline (speedup 1.0000x reference)
#include <cuda_runtime.h>
#include <cuda_bf16.h>
#include <math.h>

#define N_NODES 10000
#define N_EDGES 200000
#define NF 128

// ---- output offsets (pytree leaf order) ----
#define OFF_X     0
#define OFF_LOSS  40000
#define OFF_BETA  40001
#define OFF_RES   40002
#define OFF_X1    240002
#define OFF_X2    1520002
#define OFF_X3    2800002
#define OFF_X4    4080002
#define OFF_E1    5360002
#define OFF_E2    30960002
#define OFF_E3    56560002
#define OFF_E4    82160002

// ---- scratch (no allocations allowed) ----
__device__ float g_eam[N_EDGES * 4];
__device__ float g_xsum[N_NODES * NF];
__device__ int   g_cnt[N_NODES];
__device__ float g_loss[1];

// ---------------- utility kernels ----------------
__global__ void zero_f(float* p, int n) {
    int i = blockIdx.x * blockDim.x + threadIdx.x;
    if (i < n) p[i] = 0.f;
}
__global__ void zero_i(int* p, int n) {
    int i = blockIdx.x * blockDim.x + threadIdx.x;
    if (i < n) p[i] = 0;
}

__device__ __forceinline__ void qmul4(float qw,float qx,float qy,float qz,
                                      float rw,float rx,float ry,float rz,
                                      float& ow,float& ox,float& oy,float& oz) {
    ow = qw*rw - qx*rx - qy*ry - qz*rz;
    ox = qw*rx + qx*rw + qy*rz - qz*ry;
    oy = qw*ry - qx*rz + qy*rw + qz*rx;
    oz = qw*rz + qx*ry - qy*rx + qz*rw;
}

// eam = qmul(qmul(inv(x_org[col]), edge_attr), x_org[row]); also count rows
__global__ void prep_kernel(const float* __restrict__ x_org,
                            const float* __restrict__ edge_attr,
                            const int* __restrict__ row,
                            const int* __restrict__ col,
                            float* __restrict__ eam,
                            int* __restrict__ cnt) {
    int e = blockIdx.x * blockDim.x + threadIdx.x;
    if (e >= N_EDGES) return;
    int r = row[e], c = col[e];
    float cw = x_org[c*4+0], cx = -x_org[c*4+1], cy = -x_org[c*4+2], cz = -x_org[c*4+3];
    float aw = edge_attr[e*4+0], ax = edge_attr[e*4+1], ay = edge_attr[e*4+2], az = edge_attr[e*4+3];
    float tw,tx,ty,tz;
    qmul4(cw,cx,cy,cz, aw,ax,ay,az, tw,tx,ty,tz);
    float rw = x_org[r*4+0], rx = x_org[r*4+1], ry = x_org[r*4+2], rz = x_org[r*4+3];
    float ow,ox,oy,oz;
    qmul4(tw,tx,ty,tz, rw,rx,ry,rz, ow,ox,oy,oz);
    eam[e*4+0]=ow; eam[e*4+1]=ox; eam[e*4+2]=oy; eam[e*4+3]=oz;
    atomicAdd(&cnt[r], 1);
}

// ---------------- fused gather + GEMM ----------------
struct GemmParams {
    const float* base[6];
    int end[6];      // cumulative end in K
    int mode[6];     // 0=index by row, 1=by col, 2=by edge
    int nsegs;
    int K;
    const float* W;  // K x 128 row-major
    const float* b;  // 128
    float* e_out;    // E x 128 (relu(m))
    float* xsum;     // N x 128 (sum of m)
    const int* row;
    const int* col;
};

#define BM 64
#define BK 32

__global__ void __launch_bounds__(256)
edge_gemm_kernel(GemmParams p) {
    __shared__ float As[BM][BK + 1];
    __shared__ float Bs[BK][128];

    int tid = threadIdx.x;
    int e_base = blockIdx.x * BM;
    int lane = tid & 31, wrp = tid >> 5;

    // edges loaded by this warp in A-tile: wrp*8 .. wrp*8+7
    int lrow[8], lcol[8];
#pragma unroll
    for (int i = 0; i < 8; i++) {
        int e = e_base + wrp * 8 + i;
        lrow[i] = p.row[e];
        lcol[i] = p.col[e];
    }

    int tx = tid & 15;       // 16 groups of 8 cols
    int ty = tid >> 4;       // 16 groups of 4 edges
    float acc[4][8];
#pragma unroll
    for (int i = 0; i < 4; i++)
#pragma unroll
        for (int j = 0; j < 8; j++) acc[i][j] = 0.f;

    int nChunks = (p.K + BK - 1) / BK;
    for (int ch = 0; ch < nChunks; ch++) {
        int k0 = ch * BK;
        // ---- A tile load: lane = k, warp covers 8 edges ----
        int k = k0 + lane;
        const float* bp = nullptr; int mode = 2, width = 0, loc = 0;
        if (k < p.K) {
            int start = 0;
            for (int s = 0; s < p.nsegs; s++) {
                if (k < p.end[s]) { bp = p.base[s]; mode = p.mode[s]; width = p.end[s]-start; loc = k-start; break; }
                start = p.end[s];
            }
        }
#pragma unroll
        for (int i = 0; i < 8; i++) {
            float v = 0.f;
            if (bp) {
                int idx = (mode == 0) ? lrow[i] : ((mode == 1) ? lcol[i] : (e_base + wrp*8 + i));
                v = bp[(size_t)idx * width + loc];
            }
            As[wrp*8 + i][lane] = v;
        }
        // ---- B tile load (float4, coalesced) ----
#pragma unroll
        for (int i = 0; i < 4; i++) {
            int idx = tid + i * 256;        // 0..1023 float4's
            int kb = idx >> 5;              // 32 float4 per 128-float row
            int n4 = idx & 31;
            float4 v = make_float4(0.f,0.f,0.f,0.f);
            if (k0 + kb < p.K)
                v = reinterpret_cast<const float4*>(p.W + (size_t)(k0 + kb) * 128)[n4];
            reinterpret_cast<float4*>(&Bs[kb][0])[n4] = v;
        }
        __syncthreads();
        // ---- compute ----
#pragma unroll
        for (int kk = 0; kk < BK; kk++) {
            float a0 = As[ty*4+0][kk];
            float a1 = As[ty*4+1][kk];
            float a2 = As[ty*4+2][kk];
            float a3 = As[ty*4+3][kk];
            float4 b0 = *reinterpret_cast<const float4*>(&Bs[kk][tx*8]);
            float4 b1 = *reinterpret_cast<const float4*>(&Bs[kk][tx*8+4]);
            float bb[8] = {b0.x,b0.y,b0.z,b0.w,b1.x,b1.y,b1.z,b1.w};
#pragma unroll
            for (int j = 0; j < 8; j++) {
                acc[0][j] = fmaf(a0, bb[j], acc[0][j]);
                acc[1][j] = fmaf(a1, bb[j], acc[1][j]);
                acc[2][j] = fmaf(a2, bb[j], acc[2][j]);
                acc[3][j] = fmaf(a3, bb[j], acc[3][j]);
            }
        }
        __syncthreads();
    }

    // ---- epilogue: bias, relu->e_out, atomic sum to xsum ----
    float bias[8];
#pragma unroll
    for (int j = 0; j < 8; j++) bias[j] = p.b[tx*8 + j];
#pragma unroll
    for (int i = 0; i < 4; i++) {
        int e = e_base + ty*4 + i;
        int rnode = p.row[e];
#pragma unroll
        for (int j = 0; j < 8; j++) {
            float m = acc[i][j] + bias[j];
            p.e_out[(size_t)e * 128 + tx*8 + j] = fmaxf(m, 0.f);
            atomicAdd(&p.xsum[rnode * 128 + tx*8 + j], m);
        }
    }
}

// x_next = relu(xsum / max(cnt,1))
__global__ void node_update(const float* __restrict__ xsum,
                            const int* __restrict__ cnt,
                            float* __restrict__ xout, int n_elems) {
    int i = blockIdx.x * blockDim.x + threadIdx.x;
    if (i >= n_elems) return;
    int node = i >> 7;
    float c = (float)max(cnt[node], 1);
    xout[i] = fmaxf(xsum[i] / c, 0.f);
}

// x = normalize(qmul(x4 @ lin1_w + lin1_b, x_org))
__global__ void lin1_kernel(const float* __restrict__ x4,
                            const float* __restrict__ w,
                            const float* __restrict__ bb,
                            const float* __restrict__ x_org,
                            float* __restrict__ xout) {
    int n = blockIdx.x * blockDim.x + threadIdx.x;
    if (n >= N_NODES) return;
    float q0 = bb[0], q1 = bb[1], q2 = bb[2], q3 = bb[3];
    for (int k = 0; k < 128; k++) {
        float v = x4[(size_t)n * 128 + k];
        q0 = fmaf(v, w[k*4+0], q0);
        q1 = fmaf(v, w[k*4+1], q1);
        q2 = fmaf(v, w[k*4+2], q2);
        q3 = fmaf(v, w[k*4+3], q3);
    }
    float rw = x_org[n*4+0], rx = x_org[n*4+1], ry = x_org[n*4+2], rz = x_org[n*4+3];
    float ow,ox,oy,oz;
    qmul4(q0,q1,q2,q3, rw,rx,ry,rz, ow,ox,oy,oz);
    float nn = sqrtf(ow*ow + ox*ox + oy*oy + oz*oz);
    nn = fmaxf(nn, 1e-12f);
    xout[n*4+0] = ow/nn; xout[n*4+1] = ox/nn; xout[n*4+2] = oy/nn; xout[n*4+3] = oz/nn;
}

__global__ void loss_kernel(const float* __restrict__ gt,
                            const float* __restrict__ x,
                            const int* __restrict__ row,
                            const int* __restrict__ col,
                            const float* __restrict__ beta_p,
                            float* __restrict__ loss_acc) {
    int e = blockIdx.x * blockDim.x + threadIdx.x;
    float local = 0.f;
    if (e < N_EDGES) {
        int r = row[e], c = col[e];
        // rel_gt = qmul(gt[c], inv(gt[r]))
        float aw = gt[c*4+0], ax = gt[c*4+1], ay = gt[c*4+2], az = gt[c*4+3];
        float bw = gt[r*4+0], bx = -gt[r*4+1], by = -gt[r*4+2], bz = -gt[r*4+3];
        float gw,gx,gy,gz;
        qmul4(aw,ax,ay,az, bw,bx,by,bz, gw,gx,gy,gz);
        // rel_x = qmul(x[c], inv(x[r]))
        float cw2 = x[c*4+0], cx2 = x[c*4+1], cy2 = x[c*4+2], cz2 = x[c*4+3];
        float dw = x[r*4+0], dx = -x[r*4+1], dy = -x[r*4+2], dz = -x[r*4+3];
        float xw,xx,xy,xz;
        qmul4(cw2,cx2,cy2,cz2, dw,dx,dy,dz, xw,xx,xy,xz);
        // l1 = normalize(qmul(inv(rel_gt), rel_x))
        float lw,lx,ly,lz;
        qmul4(gw,-gx,-gy,-gz, xw,xx,xy,xz, lw,lx,ly,lz);
        float nn = sqrtf(lw*lw + lx*lx + ly*ly + lz*lz);
        nn = fmaxf(nn, 1e-12f);
        lw /= nn; lx /= nn; ly /= nn; lz /= nn;
        float beta = beta_p[0];
        float d[4] = {fabsf(lw - 1.f), fabsf(lx), fabsf(ly), fabsf(lz)};
#pragma unroll
        for (int i = 0; i < 4; i++) {
            float v = d[i];
            local += (v < beta) ? (0.5f * v * v / beta) : (v - 0.5f * beta);
        }
    }
    __shared__ float sm[256];
    sm[threadIdx.x] = local;
    __syncthreads();
    for (int s = 128; s > 0; s >>= 1) {
        if (threadIdx.x < s) sm[threadIdx.x] += sm[threadIdx.x + s];
        __syncthreads();
    }
    if (threadIdx.x == 0) atomicAdd(loss_acc, sm[0]);
}

__global__ void finalize_kernel(const float* __restrict__ loss_acc,
                                const float* __restrict__ beta_p,
                                float* __restrict__ out) {
    out[OFF_LOSS] = loss_acc[0] / (float)(N_EDGES * 4);
    out[OFF_BETA] = beta_p[0];
}

// out_res = e4 @ lin2_w + lin2_b  (warp per edge)
__global__ void outres_kernel(const float* __restrict__ e4,
                              const float* __restrict__ w,
                              const float* __restrict__ b,
                              float* __restrict__ out) {
    int gw = (blockIdx.x * blockDim.x + threadIdx.x) >> 5;
    int lane = threadIdx.x & 31;
    if (gw >= N_EDGES) return;
    float s = 0.f;
#pragma unroll
    for (int k = lane; k < 128; k += 32)
        s = fmaf(e4[(size_t)gw * 128 + k], w[k], s);
#pragma unroll
    for (int o = 16; o > 0; o >>= 1) s += __shfl_down_sync(0xFFFFFFFFu, s, o);
    if (lane == 0) out[OFF_RES + gw] = s + b[0];
}

// ---------------- host ----------------
extern "C" void kernel_launch(void* const* d_in, const int* in_sizes, int n_in,
                              void* d_out, int out_size) {
    const float* x_org     = (const float*)d_in[0];
    const float* edge_attr = (const float*)d_in[1];
    const float* gt_q      = (const float*)d_in[2];
    const float* beta      = (const float*)d_in[3];
    const float* node_feat = (const float*)d_in[4];
    const float* edge_feat = (const float*)d_in[5];
    const float* W1 = (const float*)d_in[6];
    const float* b1 = (const float*)d_in[7];
    const float* W2 = (const float*)d_in[8];
    const float* b2 = (const float*)d_in[9];
    const float* W3 = (const float*)d_in[10];
    const float* b3 = (const float*)d_in[11];
    const float* W4 = (const float*)d_in[12];
    const float* b4 = (const float*)d_in[13];
    const float* lin1_w = (const float*)d_in[14];
    const float* lin1_b = (const float*)d_in[15];
    const float* lin2_w = (const float*)d_in[16];
    const float* lin2_b = (const float*)d_in[17];
    const int* ei = (const int*)d_in[18];
    const int* row = ei;
    const int* col = ei + N_EDGES;

    float* out = (float*)d_out;
    float* x1 = out + OFF_X1;
    float* x2 = out + OFF_X2;
    float* x3 = out + OFF_X3;
    float* x4 = out + OFF_X4;
    float* e1 = out + OFF_E1;
    float* e2 = out + OFF_E2;
    float* e3 = out + OFF_E3;
    float* e4 = out + OFF_E4;

    float *eam, *xsum, *lossacc;
    int* cnt;
    cudaGetSymbolAddress((void**)&eam, g_eam);
    cudaGetSymbolAddress((void**)&xsum, g_xsum);
    cudaGetSymbolAddress((void**)&lossacc, g_loss);
    cudaGetSymbolAddress((void**)&cnt, g_cnt);

    zero_i<<<(N_NODES + 255)/256, 256>>>(cnt, N_NODES);
    zero_f<<<1, 32>>>(lossacc, 1);
    prep_kernel<<<(N_EDGES + 255)/256, 256>>>(x_org, edge_attr, row, col, eam, cnt);

    auto run_layer = [&](GemmParams& p, float* xout) {
        zero_f<<<(N_NODES*128 + 255)/256, 256>>>(xsum, N_NODES*128);
        edge_gemm_kernel<<<N_EDGES / BM, 256>>>(p);
        node_update<<<(N_NODES*128 + 255)/256, 256>>>(xsum, cnt, xout, N_NODES*128);
    };

    // Layer 1: [node_feat[row],x_org[row] | node_feat[col],x_org[col] | edge_feat,eam]
    {
        GemmParams p;
        p.base[0]=node_feat; p.mode[0]=0; p.end[0]=128;
        p.base[1]=x_org;     p.mode[1]=0; p.end[1]=132;
        p.base[2]=node_feat; p.mode[2]=1; p.end[2]=260;
        p.base[3]=x_org;     p.mode[3]=1; p.end[3]=264;
        p.base[4]=edge_feat; p.mode[4]=2; p.end[4]=392;
        p.base[5]=eam;       p.mode[5]=2; p.end[5]=396;
        p.nsegs=6; p.K=396; p.W=W1; p.b=b1; p.e_out=e1; p.xsum=xsum; p.row=row; p.col=col;
        run_layer(p, x1);
    }
    // Layer 2: [x1[row] | x1[col] | eam, e1]
    {
        GemmParams p;
        p.base[0]=x1;  p.mode[0]=0; p.end[0]=128;
        p.base[1]=x1;  p.mode[1]=1; p.end[1]=256;
        p.base[2]=eam; p.mode[2]=2; p.end[2]=260;
        p.base[3]=e1;  p.mode[3]=2; p.end[3]=388;
        p.nsegs=4; p.K=388; p.W=W2; p.b=b2; p.e_out=e2; p.xsum=xsum; p.row=row; p.col=col;
        run_layer(p, x2);
    }
    // Layer 3: [x2[row],x1[row] | x2[col],x1[col] | e2,e1]
    {
        GemmParams p;
        p.base[0]=x2; p.mode[0]=0; p.end[0]=128;
        p.base[1]=x1; p.mode[1]=0; p.end[1]=256;
        p.base[2]=x2; p.mode[2]=1; p.end[2]=384;
        p.base[3]=x1; p.mode[3]=1; p.end[3]=512;
        p.base[4]=e2; p.mode[4]=2; p.end[4]=640;
        p.base[5]=e1; p.mode[5]=2; p.end[5]=768;
        p.nsegs=6; p.K=768; p.W=W3; p.b=b3; p.e_out=e3; p.xsum=xsum; p.row=row; p.col=col;
        run_layer(p, x3);
    }
    // Layer 4: [x3[row],x2[row] | x3[col],x2[col] | e3,e2]
    {
        GemmParams p;
        p.base[0]=x3; p.mode[0]=0; p.end[0]=128;
        p.base[1]=x2; p.mode[1]=0; p.end[1]=256;
        p.base[2]=x3; p.mode[2]=1; p.end[2]=384;
        p.base[3]=x2; p.mode[3]=1; p.end[3]=512;
        p.base[4]=e3; p.mode[4]=2; p.end[4]=640;
        p.base[5]=e2; p.mode[5]=2; p.end[5]=768;
        p.nsegs=6; p.K=768; p.W=W4; p.b=b4; p.e_out=e4; p.xsum=xsum; p.row=row; p.col=col;
        run_layer(p, x4);
    }

    lin1_kernel<<<(N_NODES + 255)/256, 256>>>(x4, lin1_w, lin1_b, x_org, out + OFF_X);
    loss_kernel<<<(N_EDGES + 255)/256, 256>>>(gt_q, out + OFF_X, row, col, beta, lossacc);
    finalize_kernel<<<1, 1>>>(lossacc, beta, out);
    outres_kernel<<<(N_EDGES*32 + 255)/256, 256>>>(e4, lin2_w, lin2_b, out);

    (void)in_sizes; (void)n_in; (void)out_size;
}